// round 9
// baseline (speedup 1.0000x reference)
#include <cuda_runtime.h>
#include <math.h>

#define BATCH 4
#define CIN   64
#define COUT  64
#define H_    96
#define W_    320
#define HW    (H_ * W_)

typedef unsigned long long ull;

// packed f32x2 helpers (sm_100+)
#define FMA2(d, a, b) asm("fma.rn.f32x2 %0, %1, %2, %0;" : "+l"(d) : "l"(a), "l"(b))
__device__ __forceinline__ ull pack2(float lo, float hi) {
    ull r;
    asm("mov.b64 %0, {%1, %2};" : "=l"(r) : "f"(lo), "f"(hi));
    return r;
}
__device__ __forceinline__ void unpack2(ull v, float& lo, float& hi) {
    asm("mov.b64 {%0, %1}, %2;" : "=f"(lo), "=f"(hi) : "l"(v));
}

// ---------------- scratch (static device globals; no allocations) ----------
__device__ float g_buf[BATCH * 32];
__device__ float l_buf[BATCH * 32 * HW];
__device__ float off_buf[BATCH * 18 * HW];
__device__ float mask_buf[BATCH * 9 * HW];

// ---------------- Kernel A: tiny MLP for g (B x 32) ------------------------
__global__ void g_kernel(const float* __restrict__ scale,
                         const float* __restrict__ w1, const float* __restrict__ b1,
                         const float* __restrict__ w2, const float* __restrict__ b2)
{
    int tid = threadIdx.x;
    if (tid >= BATCH * 32) return;
    int b = tid >> 5;
    int i = tid & 31;
    const float* s = scale + b * 5;
    float bs0 = s[4] - s[2];
    float bs1 = s[3] - s[1];
    float acc = b2[i];
    for (int j = 0; j < 64; j++) {
        float h = fmaf(bs0, w1[j * 2 + 0], fmaf(bs1, w1[j * 2 + 1], b1[j]));
        h = fmaxf(h, 0.f);
        acc = fmaf(h, w2[i * 64 + j], acc);
    }
    g_buf[b * 32 + i] = acc;
}

// ---------------- Kernel B: loc conv3x3(64->32,relu) + conv1x1(32->32) -----
// half-row per block: grid = B*H*2, 160 threads, 1 px/thread
__global__ void __launch_bounds__(160) loc_kernel(const float* __restrict__ x,
    const float* __restrict__ w1, const float* __restrict__ b1,
    const float* __restrict__ w2, const float* __restrict__ b2)
{
    __shared__ float ws[32 * 9 * 32];     // [cin_local][k][cout]  36 KB
    __shared__ float w2s[32 * 32];
    __shared__ float b1s[32], b2s[32];

    int tid  = threadIdx.x;
    int half = blockIdx.x & 1;
    int bh   = blockIdx.x >> 1;
    int b    = bh / H_;
    int h    = bh % H_;
    int w    = half * 160 + tid;

    if (tid < 32) { b1s[tid] = b1[tid]; b2s[tid] = b2[tid]; }
    for (int i = tid; i < 32 * 32; i += 160) w2s[i] = w2[i];

    ull acc[16];
    #pragma unroll
    for (int j = 0; j < 16; j++) acc[j] = 0ull;

    for (int chunk = 0; chunk < 2; chunk++) {
        __syncthreads();
        for (int i = tid; i < 32 * 9 * 32; i += 160) {
            int co = i & 31;
            int t  = i >> 5;
            int k  = t % 9;
            int cl = t / 9;
            ws[i] = w1[(co * CIN + chunk * 32 + cl) * 9 + k];
        }
        __syncthreads();

        for (int cl = 0; cl < 32; cl++) {
            const float* xp = x + (size_t)((b * CIN + chunk * 32 + cl) * HW);
            float v[9];
            #pragma unroll
            for (int ky = 0; ky < 3; ky++) {
                int yy = h + ky - 1;
                bool yok = (unsigned)yy < (unsigned)H_;
                #pragma unroll
                for (int kx = 0; kx < 3; kx++) {
                    int xx = w + kx - 1;
                    bool ok = yok && ((unsigned)xx < (unsigned)W_);
                    v[ky * 3 + kx] = ok ? __ldg(xp + yy * W_ + xx) : 0.f;
                }
            }
            #pragma unroll
            for (int k = 0; k < 9; k++) {
                ull vp = pack2(v[k], v[k]);
                const ulonglong2* wq = (const ulonglong2*)(ws + (cl * 9 + k) * 32);
                #pragma unroll
                for (int j = 0; j < 8; j++) {
                    ulonglong2 q = wq[j];
                    FMA2(acc[2 * j],     vp, q.x);
                    FMA2(acc[2 * j + 1], vp, q.y);
                }
            }
        }
    }

    float a[32];
    #pragma unroll
    for (int j = 0; j < 16; j++) {
        float lo, hi; unpack2(acc[j], lo, hi);
        a[2 * j]     = fmaxf(lo + b1s[2 * j], 0.f);
        a[2 * j + 1] = fmaxf(hi + b1s[2 * j + 1], 0.f);
    }

    int base = b * 32 * HW + h * W_ + w;
    for (int c2 = 0; c2 < 32; c2++) {
        float s = b2s[c2];
        const float* wp = w2s + c2 * 32;
        #pragma unroll
        for (int c1 = 0; c1 < 32; c1++) s = fmaf(a[c1], wp[c1], s);
        l_buf[base + c2 * HW] = s;
    }
}

// ---------------- Kernel C: fuse conv3x3(cat(g,l)->32,relu) + 1x1(32->18) --
// chunk 0 (g channels, spatially constant) uses the summed-weight shortcut.
__global__ void __launch_bounds__(160) fuse_kernel(
    const float* __restrict__ w1, const float* __restrict__ b1,
    const float* __restrict__ w2, const float* __restrict__ b2)
{
    __shared__ float ws[32 * 9 * 32];     // 36 KB
    __shared__ float wsums[32 * 32];      // 4 KB: per-cl sum over k
    __shared__ float w2s[18 * 32];
    __shared__ float gs[32];
    __shared__ float b1s[32], b2s[18];

    int tid  = threadIdx.x;
    int half = blockIdx.x & 1;
    int bh   = blockIdx.x >> 1;
    int b    = bh / H_;
    int h    = bh % H_;
    int w    = half * 160 + tid;

    if (tid < 32) { b1s[tid] = b1[tid]; gs[tid] = g_buf[b * 32 + tid]; }
    if (tid < 18) b2s[tid] = b2[tid];
    for (int i = tid; i < 18 * 32; i += 160) w2s[i] = w2[i];

    ull acc[16];
    #pragma unroll
    for (int j = 0; j < 16; j++) acc[j] = 0ull;

    // ---- chunk 0: g channels (constant over space) ----
    __syncthreads();
    for (int i = tid; i < 32 * 9 * 32; i += 160) {
        int co = i & 31;
        int t  = i >> 5;
        int k  = t % 9;
        int cl = t / 9;
        ws[i] = w1[(co * 64 + cl) * 9 + k];
    }
    __syncthreads();
    for (int i = tid; i < 32 * 32; i += 160) {
        int co = i & 31;
        int cl = i >> 5;
        float s = 0.f;
        #pragma unroll
        for (int k = 0; k < 9; k++) s += ws[(cl * 9 + k) * 32 + co];
        wsums[cl * 32 + co] = s;
    }
    __syncthreads();

    bool interior = (h > 0) && (h < H_ - 1) && (w > 0) && (w < W_ - 1);
    for (int cl = 0; cl < 32; cl++) {
        float gv = gs[cl];
        ull gp = pack2(gv, gv);
        const ulonglong2* wq = (const ulonglong2*)(wsums + cl * 32);
        #pragma unroll
        for (int j = 0; j < 8; j++) {
            ulonglong2 q = wq[j];
            FMA2(acc[2 * j],     gp, q.x);
            FMA2(acc[2 * j + 1], gp, q.y);
        }
        if (!interior) {
            ull gn = pack2(-gv, -gv);
            #pragma unroll
            for (int k = 0; k < 9; k++) {
                int yy = h + k / 3 - 1;
                int xx = w + k % 3 - 1;
                if ((unsigned)yy >= (unsigned)H_ || (unsigned)xx >= (unsigned)W_) {
                    const ulonglong2* cq = (const ulonglong2*)(ws + (cl * 9 + k) * 32);
                    #pragma unroll
                    for (int j = 0; j < 8; j++) {
                        ulonglong2 q = cq[j];
                        FMA2(acc[2 * j],     gn, q.x);
                        FMA2(acc[2 * j + 1], gn, q.y);
                    }
                }
            }
        }
    }

    // ---- chunk 1: l channels ----
    __syncthreads();
    for (int i = tid; i < 32 * 9 * 32; i += 160) {
        int co = i & 31;
        int t  = i >> 5;
        int k  = t % 9;
        int cl = t / 9;
        ws[i] = w1[(co * 64 + 32 + cl) * 9 + k];
    }
    __syncthreads();

    for (int cl = 0; cl < 32; cl++) {
        const float* xp = l_buf + (size_t)((b * 32 + cl) * HW);
        float v[9];
        #pragma unroll
        for (int ky = 0; ky < 3; ky++) {
            int yy = h + ky - 1;
            bool yok = (unsigned)yy < (unsigned)H_;
            #pragma unroll
            for (int kx = 0; kx < 3; kx++) {
                int xx = w + kx - 1;
                bool ok = yok && ((unsigned)xx < (unsigned)W_);
                v[ky * 3 + kx] = ok ? __ldg(xp + yy * W_ + xx) : 0.f;
            }
        }
        #pragma unroll
        for (int k = 0; k < 9; k++) {
            ull vp = pack2(v[k], v[k]);
            const ulonglong2* wq = (const ulonglong2*)(ws + (cl * 9 + k) * 32);
            #pragma unroll
            for (int j = 0; j < 8; j++) {
                ulonglong2 q = wq[j];
                FMA2(acc[2 * j],     vp, q.x);
                FMA2(acc[2 * j + 1], vp, q.y);
            }
        }
    }

    float a[32];
    #pragma unroll
    for (int j = 0; j < 16; j++) {
        float lo, hi; unpack2(acc[j], lo, hi);
        a[2 * j]     = fmaxf(lo + b1s[2 * j], 0.f);
        a[2 * j + 1] = fmaxf(hi + b1s[2 * j + 1], 0.f);
    }

    int base = b * 18 * HW + h * W_ + w;
    for (int c2 = 0; c2 < 18; c2++) {
        float s = b2s[c2];
        const float* wp = w2s + c2 * 32;
        #pragma unroll
        for (int c1 = 0; c1 < 32; c1++) s = fmaf(a[c1], wp[c1], s);
        off_buf[base + c2 * HW] = s;
    }
}

// ---------------- Kernel D: mask conv3x3(64->9) + sigmoid ------------------
__global__ void __launch_bounds__(160) mask_kernel(const float* __restrict__ x,
    const float* __restrict__ wgt, const float* __restrict__ bias)
{
    __shared__ float ws[64 * 9 * 10];    // [cin][k][cout(pad10)]  23 KB
    __shared__ float bs[9];

    int tid  = threadIdx.x;
    int half = blockIdx.x & 1;
    int bh   = blockIdx.x >> 1;
    int b    = bh / H_;
    int h    = bh % H_;
    int w    = half * 160 + tid;

    if (tid < 9) bs[tid] = bias[tid];
    for (int i = tid; i < 64 * 9 * 10; i += 160) {
        int co = i % 10;
        int t  = i / 10;
        int k  = t % 9;
        int ci = t / 9;
        ws[i] = (co < 9) ? wgt[(co * 64 + ci) * 9 + k] : 0.f;
    }
    __syncthreads();

    ull acc[5];
    #pragma unroll
    for (int j = 0; j < 5; j++) acc[j] = 0ull;

    for (int ci = 0; ci < 64; ci++) {
        const float* xp = x + (size_t)((b * CIN + ci) * HW);
        float v[9];
        #pragma unroll
        for (int ky = 0; ky < 3; ky++) {
            int yy = h + ky - 1;
            bool yok = (unsigned)yy < (unsigned)H_;
            #pragma unroll
            for (int kx = 0; kx < 3; kx++) {
                int xx = w + kx - 1;
                bool ok = yok && ((unsigned)xx < (unsigned)W_);
                v[ky * 3 + kx] = ok ? __ldg(xp + yy * W_ + xx) : 0.f;
            }
        }
        #pragma unroll
        for (int k = 0; k < 9; k++) {
            ull vp = pack2(v[k], v[k]);
            const ull* wq = (const ull*)(ws + (ci * 9 + k) * 10);
            #pragma unroll
            for (int j = 0; j < 5; j++) FMA2(acc[j], vp, wq[j]);
        }
    }

    int base = b * 9 * HW + h * W_ + w;
    float r[10];
    #pragma unroll
    for (int j = 0; j < 5; j++) unpack2(acc[j], r[2 * j], r[2 * j + 1]);
    #pragma unroll
    for (int co = 0; co < 9; co++) {
        float s = r[co] + bs[co];
        mask_buf[base + co * HW] = 1.f / (1.f + expf(-s));
    }
}

// ---------------- Kernel E: modulated deformable conv (64->64, 3x3) --------
// grid (B*H, 2 cout-halves), 320 threads, 1 px/thread, k-outer loop.
__global__ void __launch_bounds__(320, 2) deform_kernel(const float* __restrict__ x,
    const float* __restrict__ wgt, const float* __restrict__ bias,
    float* __restrict__ out)
{
    __shared__ float ws[64 * 32];        // [cin][cout_half] for current k, 8 KB
    __shared__ float cbs[32];

    int tid = threadIdx.x;               // = w
    int bh  = blockIdx.x;
    int ch0 = blockIdx.y * 32;
    int b   = bh / H_;
    int h   = bh % H_;
    int w   = tid;

    if (tid < 32) cbs[tid] = bias[ch0 + tid];
    __syncthreads();

    ull acc[16];
    #pragma unroll
    for (int j = 0; j < 16; j++) acc[j] = pack2(cbs[2 * j], cbs[2 * j + 1]);

    const float* offp = off_buf + (size_t)(b * 18 * HW) + h * W_ + w;
    const float* mp   = mask_buf + (size_t)(b * 9 * HW) + h * W_ + w;
    const float* xb   = x + (size_t)(b * CIN * HW);

    for (int k = 0; k < 9; k++) {
        __syncthreads();
        for (int i = tid; i < 64 * 32; i += 320) {
            int co = i & 31;
            int ci = i >> 5;
            ws[i] = wgt[((ch0 + co) * 64 + ci) * 9 + k];
        }
        __syncthreads();

        int ky = k / 3 - 1;
        int kx = k % 3 - 1;
        float dy = __ldg(offp + (k * 2 + 0) * HW);
        float dx = __ldg(offp + (k * 2 + 1) * HW);
        float m  = __ldg(mp + k * HW);

        float ys = (float)(h + ky) + dy;
        float xs = (float)(w + kx) + dx;
        float fy = floorf(ys);
        float fx = floorf(xs);
        int y0 = (int)fy;
        int x0 = (int)fx;
        float wy = ys - fy;
        float wx = xs - fx;

        bool vy0 = (unsigned)y0 < (unsigned)H_;
        bool vy1 = (unsigned)(y0 + 1) < (unsigned)H_;
        bool vx0 = (unsigned)x0 < (unsigned)W_;
        bool vx1 = (unsigned)(x0 + 1) < (unsigned)W_;

        int y0c = min(max(y0, 0), H_ - 1);
        int y1c = min(max(y0 + 1, 0), H_ - 1);
        int x0c = min(max(x0, 0), W_ - 1);
        int x1c = min(max(x0 + 1, 0), W_ - 1);

        float w00 = (vy0 && vx0) ? (1.f - wy) * (1.f - wx) * m : 0.f;
        float w01 = (vy0 && vx1) ? (1.f - wy) * wx * m : 0.f;
        float w10 = (vy1 && vx0) ? wy * (1.f - wx) * m : 0.f;
        float w11 = (vy1 && vx1) ? wy * wx * m : 0.f;

        int i00 = y0c * W_ + x0c;
        int i01 = y0c * W_ + x1c;
        int i10 = y1c * W_ + x0c;
        int i11 = y1c * W_ + x1c;

        #pragma unroll 4
        for (int ci = 0; ci < 64; ci++) {
            const float* xp = xb + (size_t)(ci * HW);
            float t00 = __ldg(xp + i00);
            float t01 = __ldg(xp + i01);
            float t10 = __ldg(xp + i10);
            float t11 = __ldg(xp + i11);
            float v = w00 * t00;
            v = fmaf(w01, t01, v);
            v = fmaf(w10, t10, v);
            v = fmaf(w11, t11, v);
            ull vp = pack2(v, v);
            const ulonglong2* wq = (const ulonglong2*)(ws + ci * 32);
            #pragma unroll
            for (int j = 0; j < 8; j++) {
                ulonglong2 q = wq[j];
                FMA2(acc[2 * j],     vp, q.x);
                FMA2(acc[2 * j + 1], vp, q.y);
            }
        }
    }

    int base = b * COUT * HW + h * W_ + w;
    #pragma unroll
    for (int j = 0; j < 16; j++) {
        float lo, hi;
        unpack2(acc[j], lo, hi);
        out[base + (ch0 + 2 * j) * HW]     = lo;
        out[base + (ch0 + 2 * j + 1) * HW] = hi;
    }
}

// ---------------- launch ----------------------------------------------------
extern "C" void kernel_launch(void* const* d_in, const int* in_sizes, int n_in,
                              void* d_out, int out_size)
{
    const float* x        = (const float*)d_in[0];
    const float* scale    = (const float*)d_in[1];
    const float* glob_w1  = (const float*)d_in[2];
    const float* glob_b1  = (const float*)d_in[3];
    const float* glob_w2  = (const float*)d_in[4];
    const float* glob_b2  = (const float*)d_in[5];
    const float* loc_w1   = (const float*)d_in[6];
    const float* loc_b1   = (const float*)d_in[7];
    const float* loc_w2   = (const float*)d_in[8];
    const float* loc_b2   = (const float*)d_in[9];
    const float* fuse_w1  = (const float*)d_in[10];
    const float* fuse_b1  = (const float*)d_in[11];
    const float* fuse_w2  = (const float*)d_in[12];
    const float* fuse_b2  = (const float*)d_in[13];
    const float* mask_w   = (const float*)d_in[14];
    const float* mask_b   = (const float*)d_in[15];
    const float* conv_w   = (const float*)d_in[16];
    const float* conv_b   = (const float*)d_in[17];
    float* out = (float*)d_out;

    g_kernel<<<1, 128>>>(scale, glob_w1, glob_b1, glob_w2, glob_b2);
    loc_kernel<<<BATCH * H_ * 2, 160>>>(x, loc_w1, loc_b1, loc_w2, loc_b2);
    mask_kernel<<<BATCH * H_ * 2, 160>>>(x, mask_w, mask_b);
    fuse_kernel<<<BATCH * H_ * 2, 160>>>(fuse_w1, fuse_b1, fuse_w2, fuse_b2);
    deform_kernel<<<dim3(BATCH * H_, 2), 320>>>(x, conv_w, conv_b, out);
}

// round 10
// speedup vs baseline: 1.0026x; 1.0026x over previous
#include <cuda_runtime.h>
#include <math.h>

#define BATCH 4
#define CIN   64
#define COUT  64
#define H_    96
#define W_    320
#define HW    (H_ * W_)

typedef unsigned long long ull;

// packed f32x2 helpers (sm_100+)
#define FMA2(d, a, b) asm("fma.rn.f32x2 %0, %1, %2, %0;" : "+l"(d) : "l"(a), "l"(b))
__device__ __forceinline__ ull pack2(float lo, float hi) {
    ull r;
    asm("mov.b64 %0, {%1, %2};" : "=l"(r) : "f"(lo), "f"(hi));
    return r;
}
__device__ __forceinline__ void unpack2(ull v, float& lo, float& hi) {
    asm("mov.b64 {%0, %1}, %2;" : "=f"(lo), "=f"(hi) : "l"(v));
}

// ---------------- scratch (static device globals; no allocations) ----------
__device__ float g_buf[BATCH * 32];
__device__ float l_buf[BATCH * 32 * HW];
__device__ float off_buf[BATCH * 18 * HW];
__device__ float mask_buf[BATCH * 9 * HW];

// ---------------- Kernel A: tiny MLP for g (B x 32) ------------------------
__global__ void g_kernel(const float* __restrict__ scale,
                         const float* __restrict__ w1, const float* __restrict__ b1,
                         const float* __restrict__ w2, const float* __restrict__ b2)
{
    int tid = threadIdx.x;
    if (tid >= BATCH * 32) return;
    int b = tid >> 5;
    int i = tid & 31;
    const float* s = scale + b * 5;
    float bs0 = s[4] - s[2];
    float bs1 = s[3] - s[1];
    float acc = b2[i];
    for (int j = 0; j < 64; j++) {
        float h = fmaf(bs0, w1[j * 2 + 0], fmaf(bs1, w1[j * 2 + 1], b1[j]));
        h = fmaxf(h, 0.f);
        acc = fmaf(h, w2[i * 64 + j], acc);
    }
    g_buf[b * 32 + i] = acc;
}

// ---------------- Kernel B: loc conv3x3(64->32,relu) + conv1x1(32->32) -----
// half-row per block: grid = B*H*2, 160 threads, 1 px/thread
__global__ void __launch_bounds__(160) loc_kernel(const float* __restrict__ x,
    const float* __restrict__ w1, const float* __restrict__ b1,
    const float* __restrict__ w2, const float* __restrict__ b2)
{
    __shared__ float ws[32 * 9 * 32];     // [cin_local][k][cout]  36 KB
    __shared__ float w2s[32 * 32];
    __shared__ float b1s[32], b2s[32];

    int tid  = threadIdx.x;
    int half = blockIdx.x & 1;
    int bh   = blockIdx.x >> 1;
    int b    = bh / H_;
    int h    = bh % H_;
    int w    = half * 160 + tid;

    if (tid < 32) { b1s[tid] = b1[tid]; b2s[tid] = b2[tid]; }
    for (int i = tid; i < 32 * 32; i += 160) w2s[i] = w2[i];

    ull acc[16];
    #pragma unroll
    for (int j = 0; j < 16; j++) acc[j] = 0ull;

    for (int chunk = 0; chunk < 2; chunk++) {
        __syncthreads();
        for (int i = tid; i < 32 * 9 * 32; i += 160) {
            int co = i & 31;
            int t  = i >> 5;
            int k  = t % 9;
            int cl = t / 9;
            ws[i] = w1[(co * CIN + chunk * 32 + cl) * 9 + k];
        }
        __syncthreads();

        for (int cl = 0; cl < 32; cl++) {
            const float* xp = x + (size_t)((b * CIN + chunk * 32 + cl) * HW);
            float v[9];
            #pragma unroll
            for (int ky = 0; ky < 3; ky++) {
                int yy = h + ky - 1;
                bool yok = (unsigned)yy < (unsigned)H_;
                #pragma unroll
                for (int kx = 0; kx < 3; kx++) {
                    int xx = w + kx - 1;
                    bool ok = yok && ((unsigned)xx < (unsigned)W_);
                    v[ky * 3 + kx] = ok ? __ldg(xp + yy * W_ + xx) : 0.f;
                }
            }
            #pragma unroll
            for (int k = 0; k < 9; k++) {
                ull vp = pack2(v[k], v[k]);
                const ulonglong2* wq = (const ulonglong2*)(ws + (cl * 9 + k) * 32);
                #pragma unroll
                for (int j = 0; j < 8; j++) {
                    ulonglong2 q = wq[j];
                    FMA2(acc[2 * j],     vp, q.x);
                    FMA2(acc[2 * j + 1], vp, q.y);
                }
            }
        }
    }

    float a[32];
    #pragma unroll
    for (int j = 0; j < 16; j++) {
        float lo, hi; unpack2(acc[j], lo, hi);
        a[2 * j]     = fmaxf(lo + b1s[2 * j], 0.f);
        a[2 * j + 1] = fmaxf(hi + b1s[2 * j + 1], 0.f);
    }

    int base = b * 32 * HW + h * W_ + w;
    for (int c2 = 0; c2 < 32; c2++) {
        float s = b2s[c2];
        const float* wp = w2s + c2 * 32;
        #pragma unroll
        for (int c1 = 0; c1 < 32; c1++) s = fmaf(a[c1], wp[c1], s);
        l_buf[base + c2 * HW] = s;
    }
}

// ---------------- Kernel C: fuse conv3x3(cat(g,l)->32,relu) + 1x1(32->18) --
// chunk 0 (g channels, spatially constant) uses the summed-weight shortcut.
__global__ void __launch_bounds__(160) fuse_kernel(
    const float* __restrict__ w1, const float* __restrict__ b1,
    const float* __restrict__ w2, const float* __restrict__ b2)
{
    __shared__ float ws[32 * 9 * 32];     // 36 KB
    __shared__ float wsums[32 * 32];      // 4 KB: per-cl sum over k
    __shared__ float w2s[18 * 32];
    __shared__ float gs[32];
    __shared__ float b1s[32], b2s[18];

    int tid  = threadIdx.x;
    int half = blockIdx.x & 1;
    int bh   = blockIdx.x >> 1;
    int b    = bh / H_;
    int h    = bh % H_;
    int w    = half * 160 + tid;

    if (tid < 32) { b1s[tid] = b1[tid]; gs[tid] = g_buf[b * 32 + tid]; }
    if (tid < 18) b2s[tid] = b2[tid];
    for (int i = tid; i < 18 * 32; i += 160) w2s[i] = w2[i];

    ull acc[16];
    #pragma unroll
    for (int j = 0; j < 16; j++) acc[j] = 0ull;

    // ---- chunk 0: g channels (constant over space) ----
    __syncthreads();
    for (int i = tid; i < 32 * 9 * 32; i += 160) {
        int co = i & 31;
        int t  = i >> 5;
        int k  = t % 9;
        int cl = t / 9;
        ws[i] = w1[(co * 64 + cl) * 9 + k];
    }
    __syncthreads();
    for (int i = tid; i < 32 * 32; i += 160) {
        int co = i & 31;
        int cl = i >> 5;
        float s = 0.f;
        #pragma unroll
        for (int k = 0; k < 9; k++) s += ws[(cl * 9 + k) * 32 + co];
        wsums[cl * 32 + co] = s;
    }
    __syncthreads();

    bool interior = (h > 0) && (h < H_ - 1) && (w > 0) && (w < W_ - 1);
    for (int cl = 0; cl < 32; cl++) {
        float gv = gs[cl];
        ull gp = pack2(gv, gv);
        const ulonglong2* wq = (const ulonglong2*)(wsums + cl * 32);
        #pragma unroll
        for (int j = 0; j < 8; j++) {
            ulonglong2 q = wq[j];
            FMA2(acc[2 * j],     gp, q.x);
            FMA2(acc[2 * j + 1], gp, q.y);
        }
        if (!interior) {
            ull gn = pack2(-gv, -gv);
            #pragma unroll
            for (int k = 0; k < 9; k++) {
                int yy = h + k / 3 - 1;
                int xx = w + k % 3 - 1;
                if ((unsigned)yy >= (unsigned)H_ || (unsigned)xx >= (unsigned)W_) {
                    const ulonglong2* cq = (const ulonglong2*)(ws + (cl * 9 + k) * 32);
                    #pragma unroll
                    for (int j = 0; j < 8; j++) {
                        ulonglong2 q = cq[j];
                        FMA2(acc[2 * j],     gn, q.x);
                        FMA2(acc[2 * j + 1], gn, q.y);
                    }
                }
            }
        }
    }

    // ---- chunk 1: l channels ----
    __syncthreads();
    for (int i = tid; i < 32 * 9 * 32; i += 160) {
        int co = i & 31;
        int t  = i >> 5;
        int k  = t % 9;
        int cl = t / 9;
        ws[i] = w1[(co * 64 + 32 + cl) * 9 + k];
    }
    __syncthreads();

    for (int cl = 0; cl < 32; cl++) {
        const float* xp = l_buf + (size_t)((b * 32 + cl) * HW);
        float v[9];
        #pragma unroll
        for (int ky = 0; ky < 3; ky++) {
            int yy = h + ky - 1;
            bool yok = (unsigned)yy < (unsigned)H_;
            #pragma unroll
            for (int kx = 0; kx < 3; kx++) {
                int xx = w + kx - 1;
                bool ok = yok && ((unsigned)xx < (unsigned)W_);
                v[ky * 3 + kx] = ok ? __ldg(xp + yy * W_ + xx) : 0.f;
            }
        }
        #pragma unroll
        for (int k = 0; k < 9; k++) {
            ull vp = pack2(v[k], v[k]);
            const ulonglong2* wq = (const ulonglong2*)(ws + (cl * 9 + k) * 32);
            #pragma unroll
            for (int j = 0; j < 8; j++) {
                ulonglong2 q = wq[j];
                FMA2(acc[2 * j],     vp, q.x);
                FMA2(acc[2 * j + 1], vp, q.y);
            }
        }
    }

    float a[32];
    #pragma unroll
    for (int j = 0; j < 16; j++) {
        float lo, hi; unpack2(acc[j], lo, hi);
        a[2 * j]     = fmaxf(lo + b1s[2 * j], 0.f);
        a[2 * j + 1] = fmaxf(hi + b1s[2 * j + 1], 0.f);
    }

    int base = b * 18 * HW + h * W_ + w;
    for (int c2 = 0; c2 < 18; c2++) {
        float s = b2s[c2];
        const float* wp = w2s + c2 * 32;
        #pragma unroll
        for (int c1 = 0; c1 < 32; c1++) s = fmaf(a[c1], wp[c1], s);
        off_buf[base + c2 * HW] = s;
    }
}

// ---------------- Kernel D: mask conv3x3(64->9) + sigmoid ------------------
__global__ void __launch_bounds__(160) mask_kernel(const float* __restrict__ x,
    const float* __restrict__ wgt, const float* __restrict__ bias)
{
    __shared__ float ws[64 * 9 * 10];    // [cin][k][cout(pad10)]  23 KB
    __shared__ float bs[9];

    int tid  = threadIdx.x;
    int half = blockIdx.x & 1;
    int bh   = blockIdx.x >> 1;
    int b    = bh / H_;
    int h    = bh % H_;
    int w    = half * 160 + tid;

    if (tid < 9) bs[tid] = bias[tid];
    for (int i = tid; i < 64 * 9 * 10; i += 160) {
        int co = i % 10;
        int t  = i / 10;
        int k  = t % 9;
        int ci = t / 9;
        ws[i] = (co < 9) ? wgt[(co * 64 + ci) * 9 + k] : 0.f;
    }
    __syncthreads();

    ull acc[5];
    #pragma unroll
    for (int j = 0; j < 5; j++) acc[j] = 0ull;

    for (int ci = 0; ci < 64; ci++) {
        const float* xp = x + (size_t)((b * CIN + ci) * HW);
        float v[9];
        #pragma unroll
        for (int ky = 0; ky < 3; ky++) {
            int yy = h + ky - 1;
            bool yok = (unsigned)yy < (unsigned)H_;
            #pragma unroll
            for (int kx = 0; kx < 3; kx++) {
                int xx = w + kx - 1;
                bool ok = yok && ((unsigned)xx < (unsigned)W_);
                v[ky * 3 + kx] = ok ? __ldg(xp + yy * W_ + xx) : 0.f;
            }
        }
        #pragma unroll
        for (int k = 0; k < 9; k++) {
            ull vp = pack2(v[k], v[k]);
            const ull* wq = (const ull*)(ws + (ci * 9 + k) * 10);
            #pragma unroll
            for (int j = 0; j < 5; j++) FMA2(acc[j], vp, wq[j]);
        }
    }

    int base = b * 9 * HW + h * W_ + w;
    float r[10];
    #pragma unroll
    for (int j = 0; j < 5; j++) unpack2(acc[j], r[2 * j], r[2 * j + 1]);
    #pragma unroll
    for (int co = 0; co < 9; co++) {
        float s = r[co] + bs[co];
        mask_buf[base + co * HW] = 1.f / (1.f + expf(-s));
    }
}

// ---------------- Kernel E: modulated deformable conv (64->64, 3x3) --------
// grid (B*H, 2 cout-halves), 320 threads, 1 px/thread, k-outer loop.
__global__ void __launch_bounds__(320, 2) deform_kernel(const float* __restrict__ x,
    const float* __restrict__ wgt, const float* __restrict__ bias,
    float* __restrict__ out)
{
    __shared__ float ws[64 * 32];        // [cin][cout_half] for current k, 8 KB
    __shared__ float cbs[32];

    int tid = threadIdx.x;               // = w
    int bh  = blockIdx.x;
    int ch0 = blockIdx.y * 32;
    int b   = bh / H_;
    int h   = bh % H_;
    int w   = tid;

    if (tid < 32) cbs[tid] = bias[ch0 + tid];
    __syncthreads();

    ull acc[16];
    #pragma unroll
    for (int j = 0; j < 16; j++) acc[j] = pack2(cbs[2 * j], cbs[2 * j + 1]);

    const float* offp = off_buf + (size_t)(b * 18 * HW) + h * W_ + w;
    const float* mp   = mask_buf + (size_t)(b * 9 * HW) + h * W_ + w;
    const float* xb   = x + (size_t)(b * CIN * HW);

    for (int k = 0; k < 9; k++) {
        __syncthreads();
        for (int i = tid; i < 64 * 32; i += 320) {
            int co = i & 31;
            int ci = i >> 5;
            ws[i] = wgt[((ch0 + co) * 64 + ci) * 9 + k];
        }
        __syncthreads();

        int ky = k / 3 - 1;
        int kx = k % 3 - 1;
        float dy = __ldg(offp + (k * 2 + 0) * HW);
        float dx = __ldg(offp + (k * 2 + 1) * HW);
        float m  = __ldg(mp + k * HW);

        float ys = (float)(h + ky) + dy;
        float xs = (float)(w + kx) + dx;
        float fy = floorf(ys);
        float fx = floorf(xs);
        int y0 = (int)fy;
        int x0 = (int)fx;
        float wy = ys - fy;
        float wx = xs - fx;

        bool vy0 = (unsigned)y0 < (unsigned)H_;
        bool vy1 = (unsigned)(y0 + 1) < (unsigned)H_;
        bool vx0 = (unsigned)x0 < (unsigned)W_;
        bool vx1 = (unsigned)(x0 + 1) < (unsigned)W_;

        int y0c = min(max(y0, 0), H_ - 1);
        int y1c = min(max(y0 + 1, 0), H_ - 1);
        int x0c = min(max(x0, 0), W_ - 1);
        int x1c = min(max(x0 + 1, 0), W_ - 1);

        float w00 = (vy0 && vx0) ? (1.f - wy) * (1.f - wx) * m : 0.f;
        float w01 = (vy0 && vx1) ? (1.f - wy) * wx * m : 0.f;
        float w10 = (vy1 && vx0) ? wy * (1.f - wx) * m : 0.f;
        float w11 = (vy1 && vx1) ? wy * wx * m : 0.f;

        int i00 = y0c * W_ + x0c;
        int i01 = y0c * W_ + x1c;
        int i10 = y1c * W_ + x0c;
        int i11 = y1c * W_ + x1c;

        #pragma unroll 4
        for (int ci = 0; ci < 64; ci++) {
            const float* xp = xb + (size_t)(ci * HW);
            float t00 = __ldg(xp + i00);
            float t01 = __ldg(xp + i01);
            float t10 = __ldg(xp + i10);
            float t11 = __ldg(xp + i11);
            float v = w00 * t00;
            v = fmaf(w01, t01, v);
            v = fmaf(w10, t10, v);
            v = fmaf(w11, t11, v);
            ull vp = pack2(v, v);
            const ulonglong2* wq = (const ulonglong2*)(ws + ci * 32);
            #pragma unroll
            for (int j = 0; j < 8; j++) {
                ulonglong2 q = wq[j];
                FMA2(acc[2 * j],     vp, q.x);
                FMA2(acc[2 * j + 1], vp, q.y);
            }
        }
    }

    int base = b * COUT * HW + h * W_ + w;
    #pragma unroll
    for (int j = 0; j < 16; j++) {
        float lo, hi;
        unpack2(acc[j], lo, hi);
        out[base + (ch0 + 2 * j) * HW]     = lo;
        out[base + (ch0 + 2 * j + 1) * HW] = hi;
    }
}

// ---------------- launch ----------------------------------------------------
extern "C" void kernel_launch(void* const* d_in, const int* in_sizes, int n_in,
                              void* d_out, int out_size)
{
    const float* x        = (const float*)d_in[0];
    const float* scale    = (const float*)d_in[1];
    const float* glob_w1  = (const float*)d_in[2];
    const float* glob_b1  = (const float*)d_in[3];
    const float* glob_w2  = (const float*)d_in[4];
    const float* glob_b2  = (const float*)d_in[5];
    const float* loc_w1   = (const float*)d_in[6];
    const float* loc_b1   = (const float*)d_in[7];
    const float* loc_w2   = (const float*)d_in[8];
    const float* loc_b2   = (const float*)d_in[9];
    const float* fuse_w1  = (const float*)d_in[10];
    const float* fuse_b1  = (const float*)d_in[11];
    const float* fuse_w2  = (const float*)d_in[12];
    const float* fuse_b2  = (const float*)d_in[13];
    const float* mask_w   = (const float*)d_in[14];
    const float* mask_b   = (const float*)d_in[15];
    const float* conv_w   = (const float*)d_in[16];
    const float* conv_b   = (const float*)d_in[17];
    float* out = (float*)d_out;

    g_kernel<<<1, 128>>>(scale, glob_w1, glob_b1, glob_w2, glob_b2);
    loc_kernel<<<BATCH * H_ * 2, 160>>>(x, loc_w1, loc_b1, loc_w2, loc_b2);
    mask_kernel<<<BATCH * H_ * 2, 160>>>(x, mask_w, mask_b);
    fuse_kernel<<<BATCH * H_ * 2, 160>>>(fuse_w1, fuse_b1, fuse_w2, fuse_b2);
    deform_kernel<<<dim3(BATCH * H_, 2), 320>>>(x, conv_w, conv_b, out);
}